// round 13
// baseline (speedup 1.0000x reference)
#include <cuda_runtime.h>
#include <cuda_bf16.h>
#include <math.h>
#include <stdint.h>

#define B_    256
#define T_    128
#define WD_   300
#define DD_   50
#define IN_DIM_ 400
#define IN_PAD  416
#define ROWSP   130
#define ATTN_ 700
#define NPADA 768
#define KC3   1280
#define KA2   448
#define KE_   320
#define NSC_C 40
#define NSC_A 14
#define NF_   512
#define NCLS_ 19
#define M_    (B_*T_)
#define FEAT_ (NF_ + 2*IN_DIM_)
#define LDAB  144
#define TILE_B (128*LDAB)
#define NSTG  3
#define SMEM_BYTES (NSTG*2*TILE_B) // 110592

// grid layout for k_gemm: [0,24) cgemm, [24,1048) conv, [1048,4120) attn
#define NB_CG   24
#define NB_CONV 1024
#define NB_GEMM (NB_CG + NB_CONV + 3072)

// k_init sub-grids
#define NWT  (NF_*KC3)
#define NWA  (NPADA*KA2)
#define NW2  (NPADA*KE_)
#define NPREP (NWT + 2*NWA + 2*NW2)
#define NGATH (B_*ROWSP*IN_PAD)
#define NARGE (2*B_*KE_)
#define NB_GATH ((NGATH+255)/256)
#define NB_PREP ((NPREP+255)/256)
#define NB_ARGE ((NARGE+255)/256)
#define NB_INIT (NB_GATH + NB_PREP + NB_ARGE)

// ---------------- scratch ----------------
__device__ __nv_bfloat16  g_inpb[B_*ROWSP*IN_PAD];
__device__ __nv_bfloat16  g_Wth[NF_*KC3];
__device__ __nv_bfloat16  g_WaTh[2*NPADA*KA2];
__device__ __nv_bfloat16  g_Wa2h[2*NPADA*KE_];
__device__ __nv_bfloat16  g_argb[2*B_*KE_];
__device__ float g_c[2][B_*ATTN_];
__device__ float g_spart[2*6*M_];
__device__ float g_cnnmax[B_*NF_];
__device__ int   g_cflag;

__device__ __forceinline__ void cpa16(uint32_t dst, const void* src) {
    asm volatile("cp.async.cg.shared.global [%0], [%1], 16;\n" :: "r"(dst), "l"(src));
}
#define CP_COMMIT() asm volatile("cp.async.commit_group;\n")
#define CP_WAIT(n)  asm volatile("cp.async.wait_group %0;\n" :: "n"(n))

__device__ __forceinline__ void ldsm4(uint32_t* r, uint32_t a) {
    asm volatile("ldmatrix.sync.aligned.m8n8.x4.shared.b16 {%0,%1,%2,%3}, [%4];"
        : "=r"(r[0]), "=r"(r[1]), "=r"(r[2]), "=r"(r[3]) : "r"(a));
}

#define MMA_BF16(c, a, b) \
    asm volatile("mma.sync.aligned.m16n8k16.row.col.f32.bf16.bf16.f32 " \
        "{%0,%1,%2,%3},{%4,%5,%6,%7},{%8,%9},{%0,%1,%2,%3};" \
        : "+f"(c[0]), "+f"(c[1]), "+f"(c[2]), "+f"(c[3]) \
        : "r"(a[0]), "r"(a[1]), "r"(a[2]), "r"(a[3]), "r"(b[0]), "r"(b[1]))

// ---------------- k_init: gather + weight prep + arg embeds (merged) ----------------
__global__ void k_init(const int* __restrict__ words,
                       const int* __restrict__ d1i,
                       const int* __restrict__ d2i,
                       const float* __restrict__ wemb,
                       const float* __restrict__ d1e,
                       const float* __restrict__ d2e,
                       const float* __restrict__ mask,
                       const float* __restrict__ conv_w,
                       const float* __restrict__ Wa1,
                       const float* __restrict__ Wa2,
                       const int* __restrict__ arg1,
                       const int* __restrict__ arg2) {
    int bid = blockIdx.x;
    if (bid == 0 && threadIdx.x == 0) g_cflag = 0;
    if (bid < NB_GATH) {
        int idx = bid*256 + threadIdx.x;
        if (idx >= NGATH) return;
        int i = idx % IN_PAD;
        int r = (idx / IN_PAD) % ROWSP;
        int b = idx / (IN_PAD*ROWSP);
        float v = 0.f;
        if (r >= 1 && r <= T_ && i < IN_DIM_) {
            int m = b*T_ + (r-1);
            float x;
            if (i < WD_)            x = wemb[words[m]*WD_ + i];
            else if (i < WD_+DD_)   x = d1e[d1i[m]*DD_ + (i - WD_)];
            else                    x = d2e[d2i[m]*DD_ + (i - WD_ - DD_)];
            v = x * mask[m];
        }
        g_inpb[idx] = __float2bfloat16_rn(v);
    } else if (bid < NB_GATH + NB_PREP) {
        int idx = (bid - NB_GATH)*256 + threadIdx.x;
        if (idx >= NPREP) return;
        if (idx < NWT) {
            int o = idx / KC3, k = idx % KC3;
            float v = 0.f;
            if (k < 1248) {
                int h = k / 416, i = k - h*416;
                if (i < 400) v = conv_w[o*1200 + i*3 + h];
            }
            g_Wth[idx] = __float2bfloat16_rn(v);
        } else if (idx < NWT + 2*NWA) {
            int j = idx - NWT;
            int w = j / NWA;
            int r = j % NWA;
            int e = r / KA2, i = r % KA2;
            const float* Wa = w ? Wa2 : Wa1;
            float v = 0.f;
            if (e < ATTN_ && i < IN_DIM_) v = Wa[e*ATTN_ + i];
            g_WaTh[w*NWA + r] = __float2bfloat16_rn(v);
        } else {
            int j = idx - NWT - 2*NWA;
            int w = j / NW2;
            int r = j % NW2;
            int e = r / KE_, i = r % KE_;
            const float* Wa = w ? Wa2 : Wa1;
            float v = 0.f;
            if (e < ATTN_ && i < WD_) v = Wa[e*ATTN_ + IN_DIM_ + i];
            g_Wa2h[w*NW2 + r] = __float2bfloat16_rn(v);
        }
    } else {
        int idx = (bid - NB_GATH - NB_PREP)*256 + threadIdx.x;
        if (idx >= NARGE) return;
        int i = idx % KE_;
        int b = (idx / KE_) % B_;
        int w = idx / (B_*KE_);
        const int* arg = w ? arg2 : arg1;
        float v = (i < WD_) ? wemb[arg[b]*WD_ + i] : 0.f;
        g_argb[idx] = __float2bfloat16_rn(v);
    }
}

// ---------------- unified bf16 GEMM: cgemm / conv / attn in one grid ----------------
__global__ __launch_bounds__(256, 2) void k_gemm(const float* __restrict__ wr1,
                                                 const float* __restrict__ wr2) {
    extern __shared__ float smem[];
    uint32_t sb = (uint32_t)__cvta_generic_to_shared(smem);

    int bid = blockIdx.x;
    int tid = threadIdx.x;
    int lane = tid & 31, warp = tid >> 5;
    int warpM = warp & 1, warpN = warp >> 1;
    int g = lane >> 2, t = lane & 3;

    float acc[4][4][4];
    #pragma unroll
    for (int mi = 0; mi < 4; ++mi)
        #pragma unroll
        for (int ni = 0; ni < 4; ++ni)
            #pragma unroll
            for (int c = 0; c < 4; ++c) acc[mi][ni][c] = 0.f;

    uint32_t abuf[NSTG], bbuf[NSTG];
    #pragma unroll
    for (int s = 0; s < NSTG; ++s) {
        abuf[s] = sb + (uint32_t)(2*s)*TILE_B;
        bbuf[s] = sb + (uint32_t)(2*s + 1)*TILE_B;
    }

    int mode;                        // 2 cgemm, 0 conv, 1 attn
    int b = 0, n0, NT;
    const __nv_bfloat16* Bsrc;
    const __nv_bfloat16* Aexp = 0;
    int BK;
    int w = 0, chunk = 0, mt = 0;
    if (bid < NB_CG) {
        mode = 2;
        w = bid / 12;
        int r = bid % 12;
        mt = r / 6;
        chunk = r % 6;
        n0 = chunk * 128;
        NT = 5;
        Bsrc = &g_Wa2h[w*NW2];
        BK = KE_;
        Aexp = &g_argb[(w*B_ + mt*128)*KE_];
    } else if (bid < NB_CG + NB_CONV) {
        mode = 0;
        int id = bid - NB_CG;
        n0 = (id & 3) << 7;
        b  = id >> 2;
        NT = NSC_C/2;
        Bsrc = g_Wth;
        BK = KC3;
    } else {
        mode = 1;
        int id = bid - NB_CG - NB_CONV;
        w = id & 1;
        chunk = (id >> 1) % 6;
        b = id / 12;
        n0 = chunk * 128;
        NT = NSC_A/2;
        Bsrc = &g_WaTh[w*NWA];
        BK = KA2;
    }

    int l_row = tid >> 2, l_grp = tid & 3;
    int l_row2 = (tid + 256) >> 2, l_grp2 = (tid + 256) & 3;

    auto load_stage = [&](int st, int s) {
        #pragma unroll
        for (int sub = 0; sub < 2; ++sub) {
            int sc = 2*st + sub;
            const __nv_bfloat16* aptr;
            int astride;
            if (mode == 0) {
                int h, i0;
                if (sc < 39) { h = sc / 13; i0 = (sc - h*13) * 32; }
                else         { h = 0; i0 = 0; }
                aptr = &g_inpb[(b*ROWSP + h)*IN_PAD + i0];
                astride = IN_PAD;
            } else if (mode == 1) {
                int i0 = (sc < 13) ? sc*32 : 0;
                aptr = &g_inpb[(b*ROWSP + 1)*IN_PAD + i0];
                astride = IN_PAD;
            } else {
                aptr = Aexp + sc*32;
                astride = KE_;
            }
            int k0 = sc * 32;
            uint32_t colb = (uint32_t)(sub * 64);
            cpa16(abuf[s] + (uint32_t)(l_row*LDAB) + colb + (uint32_t)(l_grp*16),
                  aptr + l_row*astride + l_grp*8);
            cpa16(bbuf[s] + (uint32_t)(l_row*LDAB) + colb + (uint32_t)(l_grp*16),
                  &Bsrc[(n0 + l_row)*BK + k0 + l_grp*8]);
            cpa16(abuf[s] + (uint32_t)(l_row2*LDAB) + colb + (uint32_t)(l_grp2*16),
                  aptr + l_row2*astride + l_grp2*8);
            cpa16(bbuf[s] + (uint32_t)(l_row2*LDAB) + colb + (uint32_t)(l_grp2*16),
                  &Bsrc[(n0 + l_row2)*BK + k0 + l_grp2*8]);
        }
        CP_COMMIT();
    };

    uint32_t a_off[4], b_off[2];
    #pragma unroll
    for (int mi = 0; mi < 4; ++mi) {
        int row = warpM*64 + mi*16 + (lane & 15);
        a_off[mi] = (uint32_t)(row*LDAB + ((lane >> 4) << 4));
    }
    #pragma unroll
    for (int nip = 0; nip < 2; ++nip) {
        int row = warpN*32 + nip*16 + (lane & 7) + ((lane >> 4) << 3);
        b_off[nip] = (uint32_t)(row*LDAB + (((lane >> 3) & 1) << 4));
    }

    load_stage(0, 0);
    load_stage(1, 1);

    int s = 0;
    for (int st = 0; st < NT; ++st) {
        CP_WAIT(1);
        __syncthreads();
        if (st + 2 < NT) {
            int s2 = s + 2; if (s2 >= NSTG) s2 -= NSTG;
            load_stage(st + 2, s2);
        } else {
            CP_COMMIT();
        }
        #pragma unroll
        for (int ks = 0; ks < 4; ++ks) {
            uint32_t af[4][4], bf[4][2];
            #pragma unroll
            for (int mi = 0; mi < 4; ++mi)
                ldsm4(af[mi], abuf[s] + a_off[mi] + ks*32);
            #pragma unroll
            for (int nip = 0; nip < 2; ++nip)
                ldsm4(&bf[2*nip][0], bbuf[s] + b_off[nip] + ks*32);
            #pragma unroll
            for (int mi = 0; mi < 4; ++mi)
                #pragma unroll
                for (int ni = 0; ni < 4; ++ni)
                    MMA_BF16(acc[mi][ni], af[mi], bf[ni]);
        }
        if (++s >= NSTG) s = 0;
    }
    __syncthreads();

    if (mode == 0) {
        float cm[4][2];
        #pragma unroll
        for (int ni = 0; ni < 4; ++ni) { cm[ni][0] = -1e30f; cm[ni][1] = -1e30f; }
        #pragma unroll
        for (int mi = 0; mi < 4; ++mi)
            #pragma unroll
            for (int ni = 0; ni < 4; ++ni) {
                cm[ni][0] = fmaxf(cm[ni][0], fmaxf(acc[mi][ni][0], acc[mi][ni][2]));
                cm[ni][1] = fmaxf(cm[ni][1], fmaxf(acc[mi][ni][1], acc[mi][ni][3]));
            }
        #pragma unroll
        for (int off = 4; off < 32; off <<= 1)
            #pragma unroll
            for (int ni = 0; ni < 4; ++ni) {
                cm[ni][0] = fmaxf(cm[ni][0], __shfl_xor_sync(0xffffffffu, cm[ni][0], off));
                cm[ni][1] = fmaxf(cm[ni][1], __shfl_xor_sync(0xffffffffu, cm[ni][1], off));
            }
        float* smax = smem;
        if (g == 0) {
            #pragma unroll
            for (int ni = 0; ni < 4; ++ni) {
                int col = warpN*32 + ni*8 + 2*t;
                smax[warpM*128 + col]     = cm[ni][0];
                smax[warpM*128 + col + 1] = cm[ni][1];
            }
        }
        __syncthreads();
        if (tid < 128)
            g_cnnmax[b*NF_ + n0 + tid] = fmaxf(smax[tid], smax[128 + tid]);
    } else if (mode == 1) {
        // wait for cgemm blocks (wave-1, long finished by now)
        if (tid == 0) {
            while (atomicAdd(&g_cflag, 0) < NB_CG) { }
        }
        __syncthreads();
        __threadfence();
        // per-thread c/wr values for this thread's 8 columns
        const float* wr = w ? wr2 : wr1;
        const float* cb = &g_c[w][b*ATTN_];
        float cv[4][2], wv[4][2];
        #pragma unroll
        for (int ni = 0; ni < 4; ++ni)
            #pragma unroll
            for (int c = 0; c < 2; ++c) {
                int col = n0 + warpN*32 + ni*8 + 2*t + c;
                bool ok = col < ATTN_;
                cv[ni][c] = ok ? cb[col] : 0.f;
                wv[ni][c] = ok ? wr[col] : 0.f;
            }
        float rowacc[4][2];
        #pragma unroll
        for (int mi = 0; mi < 4; ++mi) {
            #pragma unroll
            for (int rr = 0; rr < 2; ++rr) {
                float rp = 0.f;
                #pragma unroll
                for (int ni = 0; ni < 4; ++ni)
                    #pragma unroll
                    for (int c = 0; c < 2; ++c)
                        rp += wv[ni][c] * tanhf(acc[mi][ni][rr*2 + c] + cv[ni][c]);
                rowacc[mi][rr] = rp;
            }
        }
        #pragma unroll
        for (int off = 1; off < 4; off <<= 1)
            #pragma unroll
            for (int mi = 0; mi < 4; ++mi)
                #pragma unroll
                for (int rr = 0; rr < 2; ++rr)
                    rowacc[mi][rr] += __shfl_xor_sync(0xffffffffu, rowacc[mi][rr], off);
        float* red = smem;
        if (t == 0) {
            #pragma unroll
            for (int mi = 0; mi < 4; ++mi)
                #pragma unroll
                for (int rr = 0; rr < 2; ++rr) {
                    int row = warpM*64 + mi*16 + g + rr*8;
                    red[warpN*128 + row] = rowacc[mi][rr];
                }
        }
        __syncthreads();
        if (tid < 128) {
            float sv = red[tid] + red[128 + tid] + red[256 + tid] + red[384 + tid];
            g_spart[(w*6 + chunk)*M_ + b*T_ + tid] = sv;
        }
    } else {
        // cgemm: store accumulators to g_c, then signal
        #pragma unroll
        for (int mi = 0; mi < 4; ++mi)
            #pragma unroll
            for (int rr = 0; rr < 2; ++rr) {
                int bb = mt*128 + warpM*64 + mi*16 + g + rr*8;
                #pragma unroll
                for (int ni = 0; ni < 4; ++ni)
                    #pragma unroll
                    for (int c = 0; c < 2; ++c) {
                        int col = n0 + warpN*32 + ni*8 + 2*t + c;
                        if (col < ATTN_)
                            g_c[w][bb*ATTN_ + col] = acc[mi][ni][rr*2 + c];
                    }
            }
        __threadfence();
        __syncthreads();
        if (tid == 0) atomicAdd(&g_cflag, 1);
    }
}

// ---------------- fused softmax + wsum + final dense + softmax ----------------
__global__ __launch_bounds__(512) void k_post(const float* __restrict__ mask,
                                              const float* __restrict__ conv_b,
                                              const float* __restrict__ dw,
                                              const float* __restrict__ db,
                                              float* __restrict__ out) {
    int b = blockIdx.x;
    int tid = threadIdx.x;
    __shared__ float aw[2][128];
    __shared__ float sh[2][128];
    __shared__ float feat[FEAT_];
    __shared__ float lg[NCLS_];
    int w = (tid >> 7) & 1, t = tid & 127;

    float s = 0.f, e = 0.f;
    if (tid < 256) {
        #pragma unroll
        for (int c = 0; c < 6; ++c) s += g_spart[(w*6 + c)*M_ + b*T_ + t];
        if (mask[b*T_ + t] == 0.f) s = -1e30f;
        sh[w][t] = s;
    }
    __syncthreads();
    for (int o = 64; o > 0; o >>= 1) {
        if (tid < 256 && t < o) sh[w][t] = fmaxf(sh[w][t], sh[w][t + o]);
        __syncthreads();
    }
    float mx = (tid < 256) ? sh[w][0] : 0.f;
    __syncthreads();
    if (tid < 256) { e = expf(s - mx); sh[w][t] = e; }
    __syncthreads();
    for (int o = 64; o > 0; o >>= 1) {
        if (tid < 256 && t < o) sh[w][t] += sh[w][t + o];
        __syncthreads();
    }
    if (tid < 256) aw[w][t] = e / sh[w][0];
    __syncthreads();

    for (int idx = tid; idx < 2*IN_DIM_; idx += 512) {
        int w2 = idx / IN_DIM_, d = idx % IN_DIM_;
        float s2 = 0.f;
        #pragma unroll 4
        for (int t2 = 0; t2 < T_; ++t2)
            s2 += aw[w2][t2] * __bfloat162float(g_inpb[(b*ROWSP + t2 + 1)*IN_PAD + d]);
        feat[NF_ + idx] = s2;
    }
    feat[tid] = tanhf(g_cnnmax[b*NF_ + tid] + conv_b[tid]);
    __syncthreads();

    int warp = tid >> 5, lane = tid & 31;
    for (int c = warp; c < NCLS_; c += 16) {
        float s3 = 0.f;
        for (int i = lane; i < FEAT_; i += 32) s3 += feat[i] * dw[c*FEAT_ + i];
        #pragma unroll
        for (int off = 16; off > 0; off >>= 1)
            s3 += __shfl_xor_sync(0xffffffffu, s3, off);
        if (lane == 0) lg[c] = s3 + db[c];
    }
    __syncthreads();
    if (tid == 0) {
        float mx2 = lg[0];
        #pragma unroll
        for (int c = 1; c < NCLS_; ++c) mx2 = fmaxf(mx2, lg[c]);
        float sm = 0.f, ee[NCLS_];
        #pragma unroll
        for (int c = 0; c < NCLS_; ++c) { ee[c] = expf(lg[c] - mx2); sm += ee[c]; }
        #pragma unroll
        for (int c = 0; c < NCLS_; ++c) out[b*NCLS_ + c] = ee[c] / sm;
    }
}

// ---------------- launch ----------------
extern "C" void kernel_launch(void* const* d_in, const int* in_sizes, int n_in,
                              void* d_out, int out_size) {
    const int*   words  = (const int*)d_in[0];
    const float* mask   = (const float*)d_in[1];
    const int*   d1i    = (const int*)d_in[2];
    const int*   d2i    = (const int*)d_in[3];
    const int*   arg1   = (const int*)d_in[7];
    const int*   arg2   = (const int*)d_in[8];
    const float* wemb   = (const float*)d_in[9];
    const float* d1e    = (const float*)d_in[10];
    const float* d2e    = (const float*)d_in[11];
    const float* Wa1    = (const float*)d_in[12];
    const float* wr1    = (const float*)d_in[13];
    const float* Wa2    = (const float*)d_in[14];
    const float* wr2    = (const float*)d_in[15];
    const float* conv_w = (const float*)d_in[16];
    const float* conv_b = (const float*)d_in[17];
    const float* dw     = (const float*)d_in[18];
    const float* db     = (const float*)d_in[19];
    float* out = (float*)d_out;

    cudaFuncSetAttribute(k_gemm, cudaFuncAttributeMaxDynamicSharedMemorySize, SMEM_BYTES);

    k_init<<<NB_INIT, 256>>>(words, d1i, d2i, wemb, d1e, d2e, mask,
                             conv_w, Wa1, Wa2, arg1, arg2);
    k_gemm<<<NB_GEMM, 256, SMEM_BYTES>>>(wr1, wr2);
    k_post<<<B_, 512>>>(mask, conv_b, dw, db, out);
}

// round 14
// speedup vs baseline: 1.1040x; 1.1040x over previous
#include <cuda_runtime.h>
#include <cuda_bf16.h>
#include <math.h>
#include <stdint.h>

#define B_    256
#define T_    128
#define WD_   300
#define DD_   50
#define IN_DIM_ 400
#define IN_PAD  416
#define ROWSP   130
#define ATTN_ 700
#define NPADA 768
#define KC3   1280
#define KA2   448
#define KE_   320
#define NSC_C 40
#define NSC_A 14
#define NF_   512
#define NCLS_ 19
#define M_    (B_*T_)
#define FEAT_ (NF_ + 2*IN_DIM_)
#define LDAB  144
#define TILE_B (128*LDAB)
#define NSTG  3
#define SMEM_BYTES (NSTG*2*TILE_B) // 110592

// grid layout for k_gemm: [0,24) cgemm, [24,1048) conv, [1048,4120) attn
#define NB_CG   24
#define NB_CONV 1024
#define NB_GEMM (NB_CG + NB_CONV + 3072)

// k_init segments (unit = 4 elements)
#define NWT  (NF_*KC3)
#define NWA  (NPADA*KA2)
#define NW2  (NPADA*KE_)
#define NPREP (NWT + 2*NWA + 2*NW2)
#define NGATH (B_*ROWSP*IN_PAD)
#define NARGE (2*B_*KE_)
#define NB_GATH ((NGATH/4 + 255)/256)
#define NB_PREP ((NPREP/4 + 255)/256)
#define NB_ARGE ((NARGE/4 + 255)/256)
#define NB_INIT (NB_GATH + NB_PREP + NB_ARGE)

// ---------------- scratch ----------------
__device__ __nv_bfloat16  g_inpb[B_*ROWSP*IN_PAD];
__device__ __nv_bfloat16  g_Wth[NF_*KC3];
__device__ __nv_bfloat16  g_WaTh[2*NPADA*KA2];
__device__ __nv_bfloat16  g_Wa2h[2*NPADA*KE_];
__device__ __nv_bfloat16  g_argb[2*B_*KE_];
__device__ float g_c[2][B_*ATTN_];
__device__ float g_spart[2*6*M_];
__device__ float g_cnnmax[B_*NF_];
__device__ int   g_cflag;

__device__ __forceinline__ void cpa16(uint32_t dst, const void* src) {
    asm volatile("cp.async.cg.shared.global [%0], [%1], 16;\n" :: "r"(dst), "l"(src));
}
#define CP_COMMIT() asm volatile("cp.async.commit_group;\n")
#define CP_WAIT(n)  asm volatile("cp.async.wait_group %0;\n" :: "n"(n))

__device__ __forceinline__ void ldsm4(uint32_t* r, uint32_t a) {
    asm volatile("ldmatrix.sync.aligned.m8n8.x4.shared.b16 {%0,%1,%2,%3}, [%4];"
        : "=r"(r[0]), "=r"(r[1]), "=r"(r[2]), "=r"(r[3]) : "r"(a));
}

#define MMA_BF16(c, a, b) \
    asm volatile("mma.sync.aligned.m16n8k16.row.col.f32.bf16.bf16.f32 " \
        "{%0,%1,%2,%3},{%4,%5,%6,%7},{%8,%9},{%0,%1,%2,%3};" \
        : "+f"(c[0]), "+f"(c[1]), "+f"(c[2]), "+f"(c[3]) \
        : "r"(a[0]), "r"(a[1]), "r"(a[2]), "r"(a[3]), "r"(b[0]), "r"(b[1]))

__device__ __forceinline__ uint2 pack4(float a, float b, float c, float d) {
    __nv_bfloat162 lo = __floats2bfloat162_rn(a, b);
    __nv_bfloat162 hi = __floats2bfloat162_rn(c, d);
    uint2 r;
    r.x = *reinterpret_cast<uint32_t*>(&lo);
    r.y = *reinterpret_cast<uint32_t*>(&hi);
    return r;
}

// ---------------- k_init: 4 elements/thread, vectorized ----------------
__global__ void k_init(const int* __restrict__ words,
                       const int* __restrict__ d1i,
                       const int* __restrict__ d2i,
                       const float* __restrict__ wemb,
                       const float* __restrict__ d1e,
                       const float* __restrict__ d2e,
                       const float* __restrict__ mask,
                       const float* __restrict__ conv_w,
                       const float* __restrict__ Wa1,
                       const float* __restrict__ Wa2,
                       const int* __restrict__ arg1,
                       const int* __restrict__ arg2) {
    int bid = blockIdx.x;
    if (bid == 0 && threadIdx.x == 0) g_cflag = 0;

    if (bid < NB_GATH) {
        int idx = bid*256 + threadIdx.x;
        if (idx >= NGATH/4) return;
        int e4 = idx*4;
        int i0 = e4 % IN_PAD;                 // multiple of 4
        int r  = (e4 / IN_PAD) % ROWSP;
        int b  = e4 / (IN_PAD*ROWSP);
        float v0 = 0.f, v1 = 0.f, v2 = 0.f, v3 = 0.f;
        if (r >= 1 && r <= T_ && i0 < IN_DIM_) {
            int m = b*T_ + (r-1);
            float mv = mask[m];
            if (mv != 0.f) {
                if (i0 + 3 < WD_) {           // fast path: word region, aligned
                    float4 x = *reinterpret_cast<const float4*>(&wemb[words[m]*WD_ + i0]);
                    v0 = x.x; v1 = x.y; v2 = x.z; v3 = x.w;
                } else {
                    int wd = words[m], i1 = d1i[m], i2 = d2i[m];
                    float t[4];
                    #pragma unroll
                    for (int j = 0; j < 4; ++j) {
                        int i = i0 + j;
                        float x;
                        if (i < WD_)            x = wemb[wd*WD_ + i];
                        else if (i < WD_+DD_)   x = d1e[i1*DD_ + (i - WD_)];
                        else                    x = d2e[i2*DD_ + (i - WD_ - DD_)];
                        t[j] = x;
                    }
                    v0 = t[0]; v1 = t[1]; v2 = t[2]; v3 = t[3];
                }
                v0 *= mv; v1 *= mv; v2 *= mv; v3 *= mv;
            }
        }
        reinterpret_cast<uint2*>(g_inpb)[idx] = pack4(v0, v1, v2, v3);
    } else if (bid < NB_GATH + NB_PREP) {
        int idx = (bid - NB_GATH)*256 + threadIdx.x;
        if (idx >= NPREP/4) return;
        int e4 = idx*4;
        uint2 outv;
        if (e4 < NWT) {
            int o = e4 / KC3, k0 = e4 % KC3;   // chunk-uniform region
            float v0 = 0.f, v1 = 0.f, v2 = 0.f, v3 = 0.f;
            if (k0 < 1248) {
                int h = k0 / 416, i0 = k0 - h*416;
                if (i0 < 400) {
                    const float* src = &conv_w[o*1200 + i0*3 + h];
                    v0 = src[0]; v1 = src[3]; v2 = src[6]; v3 = src[9];
                }
            }
            outv = pack4(v0, v1, v2, v3);
            reinterpret_cast<uint2*>(g_Wth)[idx] = outv;
        } else if (e4 < NWT + 2*NWA) {
            int j4 = e4 - NWT;
            int w = j4 / NWA;
            int r = j4 % NWA;
            int e = r / KA2, i0 = r % KA2;
            float v0 = 0.f, v1 = 0.f, v2 = 0.f, v3 = 0.f;
            if (e < ATTN_ && i0 < IN_DIM_) {
                const float* Wa = w ? Wa2 : Wa1;
                float4 x = *reinterpret_cast<const float4*>(&Wa[e*ATTN_ + i0]);
                v0 = x.x; v1 = x.y; v2 = x.z; v3 = x.w;
            }
            outv = pack4(v0, v1, v2, v3);
            reinterpret_cast<uint2*>(g_WaTh)[j4/4] = outv;
        } else {
            int j4 = e4 - NWT - 2*NWA;
            int w = j4 / NW2;
            int r = j4 % NW2;
            int e = r / KE_, i0 = r % KE_;
            float v0 = 0.f, v1 = 0.f, v2 = 0.f, v3 = 0.f;
            if (e < ATTN_ && i0 < WD_) {
                const float* Wa = w ? Wa2 : Wa1;
                float4 x = *reinterpret_cast<const float4*>(&Wa[e*ATTN_ + IN_DIM_ + i0]);
                v0 = x.x; v1 = x.y; v2 = x.z; v3 = x.w;
            }
            outv = pack4(v0, v1, v2, v3);
            reinterpret_cast<uint2*>(g_Wa2h)[j4/4] = outv;
        }
    } else {
        int idx = (bid - NB_GATH - NB_PREP)*256 + threadIdx.x;
        if (idx >= NARGE/4) return;
        int e4 = idx*4;
        int i0 = e4 % KE_;
        int b  = (e4 / KE_) % B_;
        int w  = e4 / (B_*KE_);
        const int* arg = w ? arg2 : arg1;
        float v0 = 0.f, v1 = 0.f, v2 = 0.f, v3 = 0.f;
        if (i0 < WD_) {
            float4 x = *reinterpret_cast<const float4*>(&wemb[arg[b]*WD_ + i0]);
            v0 = x.x; v1 = x.y; v2 = x.z; v3 = x.w;
        }
        reinterpret_cast<uint2*>(g_argb)[idx] = pack4(v0, v1, v2, v3);
    }
}

// ---------------- unified bf16 GEMM: cgemm / conv / attn in one grid ----------------
__global__ __launch_bounds__(256, 2) void k_gemm(const float* __restrict__ wr1,
                                                 const float* __restrict__ wr2) {
    extern __shared__ float smem[];
    uint32_t sb = (uint32_t)__cvta_generic_to_shared(smem);

    int bid = blockIdx.x;
    int tid = threadIdx.x;
    int lane = tid & 31, warp = tid >> 5;
    int warpM = warp & 1, warpN = warp >> 1;
    int g = lane >> 2, t = lane & 3;

    float acc[4][4][4];
    #pragma unroll
    for (int mi = 0; mi < 4; ++mi)
        #pragma unroll
        for (int ni = 0; ni < 4; ++ni)
            #pragma unroll
            for (int c = 0; c < 4; ++c) acc[mi][ni][c] = 0.f;

    uint32_t abuf[NSTG], bbuf[NSTG];
    #pragma unroll
    for (int s = 0; s < NSTG; ++s) {
        abuf[s] = sb + (uint32_t)(2*s)*TILE_B;
        bbuf[s] = sb + (uint32_t)(2*s + 1)*TILE_B;
    }

    int mode;                        // 2 cgemm, 0 conv, 1 attn
    int b = 0, n0, NT;
    const __nv_bfloat16* Bsrc;
    const __nv_bfloat16* Aexp = 0;
    int BK;
    int w = 0, chunk = 0, mt = 0;
    if (bid < NB_CG) {
        mode = 2;
        w = bid / 12;
        int r = bid % 12;
        mt = r / 6;
        chunk = r % 6;
        n0 = chunk * 128;
        NT = 5;
        Bsrc = &g_Wa2h[w*NW2];
        BK = KE_;
        Aexp = &g_argb[(w*B_ + mt*128)*KE_];
    } else if (bid < NB_CG + NB_CONV) {
        mode = 0;
        int id = bid - NB_CG;
        n0 = (id & 3) << 7;
        b  = id >> 2;
        NT = NSC_C/2;
        Bsrc = g_Wth;
        BK = KC3;
    } else {
        mode = 1;
        int id = bid - NB_CG - NB_CONV;
        w = id & 1;
        chunk = (id >> 1) % 6;
        b = id / 12;
        n0 = chunk * 128;
        NT = NSC_A/2;
        Bsrc = &g_WaTh[w*NWA];
        BK = KA2;
    }

    int l_row = tid >> 2, l_grp = tid & 3;
    int l_row2 = (tid + 256) >> 2, l_grp2 = (tid + 256) & 3;

    auto load_stage = [&](int st, int s) {
        #pragma unroll
        for (int sub = 0; sub < 2; ++sub) {
            int sc = 2*st + sub;
            const __nv_bfloat16* aptr;
            int astride;
            if (mode == 0) {
                int h, i0;
                if (sc < 39) { h = sc / 13; i0 = (sc - h*13) * 32; }
                else         { h = 0; i0 = 0; }
                aptr = &g_inpb[(b*ROWSP + h)*IN_PAD + i0];
                astride = IN_PAD;
            } else if (mode == 1) {
                int i0 = (sc < 13) ? sc*32 : 0;
                aptr = &g_inpb[(b*ROWSP + 1)*IN_PAD + i0];
                astride = IN_PAD;
            } else {
                aptr = Aexp + sc*32;
                astride = KE_;
            }
            int k0 = sc * 32;
            uint32_t colb = (uint32_t)(sub * 64);
            cpa16(abuf[s] + (uint32_t)(l_row*LDAB) + colb + (uint32_t)(l_grp*16),
                  aptr + l_row*astride + l_grp*8);
            cpa16(bbuf[s] + (uint32_t)(l_row*LDAB) + colb + (uint32_t)(l_grp*16),
                  &Bsrc[(n0 + l_row)*BK + k0 + l_grp*8]);
            cpa16(abuf[s] + (uint32_t)(l_row2*LDAB) + colb + (uint32_t)(l_grp2*16),
                  aptr + l_row2*astride + l_grp2*8);
            cpa16(bbuf[s] + (uint32_t)(l_row2*LDAB) + colb + (uint32_t)(l_grp2*16),
                  &Bsrc[(n0 + l_row2)*BK + k0 + l_grp2*8]);
        }
        CP_COMMIT();
    };

    uint32_t a_off[4], b_off[2];
    #pragma unroll
    for (int mi = 0; mi < 4; ++mi) {
        int row = warpM*64 + mi*16 + (lane & 15);
        a_off[mi] = (uint32_t)(row*LDAB + ((lane >> 4) << 4));
    }
    #pragma unroll
    for (int nip = 0; nip < 2; ++nip) {
        int row = warpN*32 + nip*16 + (lane & 7) + ((lane >> 4) << 3);
        b_off[nip] = (uint32_t)(row*LDAB + (((lane >> 3) & 1) << 4));
    }

    load_stage(0, 0);
    load_stage(1, 1);

    int s = 0;
    for (int st = 0; st < NT; ++st) {
        CP_WAIT(1);
        __syncthreads();
        if (st + 2 < NT) {
            int s2 = s + 2; if (s2 >= NSTG) s2 -= NSTG;
            load_stage(st + 2, s2);
        } else {
            CP_COMMIT();
        }
        #pragma unroll
        for (int ks = 0; ks < 4; ++ks) {
            uint32_t af[4][4], bf[4][2];
            #pragma unroll
            for (int mi = 0; mi < 4; ++mi)
                ldsm4(af[mi], abuf[s] + a_off[mi] + ks*32);
            #pragma unroll
            for (int nip = 0; nip < 2; ++nip)
                ldsm4(&bf[2*nip][0], bbuf[s] + b_off[nip] + ks*32);
            #pragma unroll
            for (int mi = 0; mi < 4; ++mi)
                #pragma unroll
                for (int ni = 0; ni < 4; ++ni)
                    MMA_BF16(acc[mi][ni], af[mi], bf[ni]);
        }
        if (++s >= NSTG) s = 0;
    }
    __syncthreads();

    if (mode == 0) {
        float cm[4][2];
        #pragma unroll
        for (int ni = 0; ni < 4; ++ni) { cm[ni][0] = -1e30f; cm[ni][1] = -1e30f; }
        #pragma unroll
        for (int mi = 0; mi < 4; ++mi)
            #pragma unroll
            for (int ni = 0; ni < 4; ++ni) {
                cm[ni][0] = fmaxf(cm[ni][0], fmaxf(acc[mi][ni][0], acc[mi][ni][2]));
                cm[ni][1] = fmaxf(cm[ni][1], fmaxf(acc[mi][ni][1], acc[mi][ni][3]));
            }
        #pragma unroll
        for (int off = 4; off < 32; off <<= 1)
            #pragma unroll
            for (int ni = 0; ni < 4; ++ni) {
                cm[ni][0] = fmaxf(cm[ni][0], __shfl_xor_sync(0xffffffffu, cm[ni][0], off));
                cm[ni][1] = fmaxf(cm[ni][1], __shfl_xor_sync(0xffffffffu, cm[ni][1], off));
            }
        float* smax = smem;
        if (g == 0) {
            #pragma unroll
            for (int ni = 0; ni < 4; ++ni) {
                int col = warpN*32 + ni*8 + 2*t;
                smax[warpM*128 + col]     = cm[ni][0];
                smax[warpM*128 + col + 1] = cm[ni][1];
            }
        }
        __syncthreads();
        if (tid < 128)
            g_cnnmax[b*NF_ + n0 + tid] = fmaxf(smax[tid], smax[128 + tid]);
    } else if (mode == 1) {
        if (tid == 0) {
            while (atomicAdd(&g_cflag, 0) < NB_CG) { }
        }
        __syncthreads();
        __threadfence();
        const float* wr = w ? wr2 : wr1;
        const float* cb = &g_c[w][b*ATTN_];
        float cv[4][2], wv[4][2];
        #pragma unroll
        for (int ni = 0; ni < 4; ++ni)
            #pragma unroll
            for (int c = 0; c < 2; ++c) {
                int col = n0 + warpN*32 + ni*8 + 2*t + c;
                bool ok = col < ATTN_;
                cv[ni][c] = ok ? cb[col] : 0.f;
                wv[ni][c] = ok ? wr[col] : 0.f;
            }
        float rowacc[4][2];
        #pragma unroll
        for (int mi = 0; mi < 4; ++mi) {
            #pragma unroll
            for (int rr = 0; rr < 2; ++rr) {
                float rp = 0.f;
                #pragma unroll
                for (int ni = 0; ni < 4; ++ni)
                    #pragma unroll
                    for (int c = 0; c < 2; ++c)
                        rp += wv[ni][c] * tanhf(acc[mi][ni][rr*2 + c] + cv[ni][c]);
                rowacc[mi][rr] = rp;
            }
        }
        #pragma unroll
        for (int off = 1; off < 4; off <<= 1)
            #pragma unroll
            for (int mi = 0; mi < 4; ++mi)
                #pragma unroll
                for (int rr = 0; rr < 2; ++rr)
                    rowacc[mi][rr] += __shfl_xor_sync(0xffffffffu, rowacc[mi][rr], off);
        float* red = smem;
        if (t == 0) {
            #pragma unroll
            for (int mi = 0; mi < 4; ++mi)
                #pragma unroll
                for (int rr = 0; rr < 2; ++rr) {
                    int row = warpM*64 + mi*16 + g + rr*8;
                    red[warpN*128 + row] = rowacc[mi][rr];
                }
        }
        __syncthreads();
        if (tid < 128) {
            float sv = red[tid] + red[128 + tid] + red[256 + tid] + red[384 + tid];
            g_spart[(w*6 + chunk)*M_ + b*T_ + tid] = sv;
        }
    } else {
        #pragma unroll
        for (int mi = 0; mi < 4; ++mi)
            #pragma unroll
            for (int rr = 0; rr < 2; ++rr) {
                int bb = mt*128 + warpM*64 + mi*16 + g + rr*8;
                #pragma unroll
                for (int ni = 0; ni < 4; ++ni)
                    #pragma unroll
                    for (int c = 0; c < 2; ++c) {
                        int col = n0 + warpN*32 + ni*8 + 2*t + c;
                        if (col < ATTN_)
                            g_c[w][bb*ATTN_ + col] = acc[mi][ni][rr*2 + c];
                    }
            }
        __threadfence();
        __syncthreads();
        if (tid == 0) atomicAdd(&g_cflag, 1);
    }
}

// ---------------- fused softmax + wsum + final dense + softmax ----------------
__global__ __launch_bounds__(512) void k_post(const float* __restrict__ mask,
                                              const float* __restrict__ conv_b,
                                              const float* __restrict__ dw,
                                              const float* __restrict__ db,
                                              float* __restrict__ out) {
    int b = blockIdx.x;
    int tid = threadIdx.x;
    __shared__ float aw[2][128];
    __shared__ float sh[2][128];
    __shared__ float feat[FEAT_];
    __shared__ float lg[NCLS_];
    int w = (tid >> 7) & 1, t = tid & 127;

    float s = 0.f, e = 0.f;
    if (tid < 256) {
        #pragma unroll
        for (int c = 0; c < 6; ++c) s += g_spart[(w*6 + c)*M_ + b*T_ + t];
        if (mask[b*T_ + t] == 0.f) s = -1e30f;
        sh[w][t] = s;
    }
    __syncthreads();
    for (int o = 64; o > 0; o >>= 1) {
        if (tid < 256 && t < o) sh[w][t] = fmaxf(sh[w][t], sh[w][t + o]);
        __syncthreads();
    }
    float mx = (tid < 256) ? sh[w][0] : 0.f;
    __syncthreads();
    if (tid < 256) { e = expf(s - mx); sh[w][t] = e; }
    __syncthreads();
    for (int o = 64; o > 0; o >>= 1) {
        if (tid < 256 && t < o) sh[w][t] += sh[w][t + o];
        __syncthreads();
    }
    if (tid < 256) aw[w][t] = e / sh[w][0];
    __syncthreads();

    for (int idx = tid; idx < 2*IN_DIM_; idx += 512) {
        int w2 = idx / IN_DIM_, d = idx % IN_DIM_;
        float s2 = 0.f;
        #pragma unroll 4
        for (int t2 = 0; t2 < T_; ++t2)
            s2 += aw[w2][t2] * __bfloat162float(g_inpb[(b*ROWSP + t2 + 1)*IN_PAD + d]);
        feat[NF_ + idx] = s2;
    }
    feat[tid] = tanhf(g_cnnmax[b*NF_ + tid] + conv_b[tid]);
    __syncthreads();

    int warp = tid >> 5, lane = tid & 31;
    for (int c = warp; c < NCLS_; c += 16) {
        float s3 = 0.f;
        for (int i = lane; i < FEAT_; i += 32) s3 += feat[i] * dw[c*FEAT_ + i];
        #pragma unroll
        for (int off = 16; off > 0; off >>= 1)
            s3 += __shfl_xor_sync(0xffffffffu, s3, off);
        if (lane == 0) lg[c] = s3 + db[c];
    }
    __syncthreads();
    if (tid == 0) {
        float mx2 = lg[0];
        #pragma unroll
        for (int c = 1; c < NCLS_; ++c) mx2 = fmaxf(mx2, lg[c]);
        float sm = 0.f, ee[NCLS_];
        #pragma unroll
        for (int c = 0; c < NCLS_; ++c) { ee[c] = expf(lg[c] - mx2); sm += ee[c]; }
        #pragma unroll
        for (int c = 0; c < NCLS_; ++c) out[b*NCLS_ + c] = ee[c] / sm;
    }
}

// ---------------- launch ----------------
extern "C" void kernel_launch(void* const* d_in, const int* in_sizes, int n_in,
                              void* d_out, int out_size) {
    const int*   words  = (const int*)d_in[0];
    const float* mask   = (const float*)d_in[1];
    const int*   d1i    = (const int*)d_in[2];
    const int*   d2i    = (const int*)d_in[3];
    const int*   arg1   = (const int*)d_in[7];
    const int*   arg2   = (const int*)d_in[8];
    const float* wemb   = (const float*)d_in[9];
    const float* d1e    = (const float*)d_in[10];
    const float* d2e    = (const float*)d_in[11];
    const float* Wa1    = (const float*)d_in[12];
    const float* wr1    = (const float*)d_in[13];
    const float* Wa2    = (const float*)d_in[14];
    const float* wr2    = (const float*)d_in[15];
    const float* conv_w = (const float*)d_in[16];
    const float* conv_b = (const float*)d_in[17];
    const float* dw     = (const float*)d_in[18];
    const float* db     = (const float*)d_in[19];
    float* out = (float*)d_out;

    cudaFuncSetAttribute(k_gemm, cudaFuncAttributeMaxDynamicSharedMemorySize, SMEM_BYTES);

    k_init<<<NB_INIT, 256>>>(words, d1i, d2i, wemb, d1e, d2e, mask,
                             conv_w, Wa1, Wa2, arg1, arg2);
    k_gemm<<<NB_GEMM, 256, SMEM_BYTES>>>(wr1, wr2);
    k_post<<<B_, 512>>>(mask, conv_b, dw, db, out);
}

// round 15
// speedup vs baseline: 1.1274x; 1.0212x over previous
#include <cuda_runtime.h>
#include <cuda_bf16.h>
#include <math.h>
#include <stdint.h>

#define B_    256
#define T_    128
#define WD_   300
#define DD_   50
#define IN_DIM_ 400
#define IN_PAD  416
#define ROWSP   130
#define ATTN_ 700
#define NA_CM 1408                 // combined attn N (2*700 padded to 11*128)
#define NCH_A 11
#define NPC   768                  // cgemm N padding
#define KC3   1280
#define KA2   448
#define KE_   320
#define NSC_C 40
#define NF_   512
#define NCLS_ 19
#define M_    (B_*T_)
#define FEAT_ (NF_ + 2*IN_DIM_)
#define LDAB  144
#define TILE_B (128*LDAB)
#define NSTG  3
#define SMEM_BYTES (NSTG*2*TILE_B) // 110592

// grid: [0,24) cgemm, [24,1048) conv, [1048, 1048+2816) attn
#define NB_CG   24
#define NB_CONV 1024
#define NB_ATTN (B_*NCH_A)
#define NB_GEMM (NB_CG + NB_CONV + NB_ATTN)

// k_init segments (unit = 4 elements)
#define NWT   (NF_*KC3)
#define NWAC  (NA_CM*KA2)
#define NW2   (NPC*KE_)
#define NPREP (NWT + NWAC + 2*NW2)
#define NGATH (B_*ROWSP*IN_PAD)
#define NARGE (2*B_*KE_)
#define NB_GATH ((NGATH/4 + 255)/256)
#define NB_PREP ((NPREP/4 + 255)/256)
#define NB_ARGE ((NARGE/4 + 255)/256)
#define NB_WRC  ((NA_CM/4 + 255)/256)
#define NB_INIT (NB_GATH + NB_PREP + NB_ARGE + NB_WRC)

// ---------------- scratch ----------------
__device__ __nv_bfloat16  g_inpb[B_*ROWSP*IN_PAD];
__device__ __nv_bfloat16  g_Wth[NF_*KC3];
__device__ __nv_bfloat16  g_WaTh[NA_CM*KA2];         // combined [e'][i]
__device__ __nv_bfloat16  g_Wa2h[2*NPC*KE_];
__device__ __nv_bfloat16  g_argb[2*B_*KE_];
__device__ float g_cc[B_*NA_CM];                     // combined c [b][w*700+e]
__device__ float g_wrc[NA_CM];                       // combined wr
__device__ float g_spart[2*NCH_A*M_];                // plane = chunk*2 + w
__device__ float g_cnnmax[B_*NF_];
__device__ int   g_cflag;

__device__ __forceinline__ void cpa16(uint32_t dst, const void* src) {
    asm volatile("cp.async.cg.shared.global [%0], [%1], 16;\n" :: "r"(dst), "l"(src));
}
#define CP_COMMIT() asm volatile("cp.async.commit_group;\n")
#define CP_WAIT(n)  asm volatile("cp.async.wait_group %0;\n" :: "n"(n))

__device__ __forceinline__ void ldsm4(uint32_t* r, uint32_t a) {
    asm volatile("ldmatrix.sync.aligned.m8n8.x4.shared.b16 {%0,%1,%2,%3}, [%4];"
        : "=r"(r[0]), "=r"(r[1]), "=r"(r[2]), "=r"(r[3]) : "r"(a));
}

#define MMA_BF16(c, a, b) \
    asm volatile("mma.sync.aligned.m16n8k16.row.col.f32.bf16.bf16.f32 " \
        "{%0,%1,%2,%3},{%4,%5,%6,%7},{%8,%9},{%0,%1,%2,%3};" \
        : "+f"(c[0]), "+f"(c[1]), "+f"(c[2]), "+f"(c[3]) \
        : "r"(a[0]), "r"(a[1]), "r"(a[2]), "r"(a[3]), "r"(b[0]), "r"(b[1]))

__device__ __forceinline__ uint2 pack4(float a, float b, float c, float d) {
    __nv_bfloat162 lo = __floats2bfloat162_rn(a, b);
    __nv_bfloat162 hi = __floats2bfloat162_rn(c, d);
    uint2 r;
    r.x = *reinterpret_cast<uint32_t*>(&lo);
    r.y = *reinterpret_cast<uint32_t*>(&hi);
    return r;
}

// ---------------- k_init: 4 elements/thread, vectorized ----------------
__global__ void k_init(const int* __restrict__ words,
                       const int* __restrict__ d1i,
                       const int* __restrict__ d2i,
                       const float* __restrict__ wemb,
                       const float* __restrict__ d1e,
                       const float* __restrict__ d2e,
                       const float* __restrict__ mask,
                       const float* __restrict__ conv_w,
                       const float* __restrict__ Wa1,
                       const float* __restrict__ Wa2,
                       const int* __restrict__ arg1,
                       const int* __restrict__ arg2,
                       const float* __restrict__ wr1,
                       const float* __restrict__ wr2) {
    int bid = blockIdx.x;
    if (bid == 0 && threadIdx.x == 0) g_cflag = 0;

    if (bid < NB_GATH) {
        int idx = bid*256 + threadIdx.x;
        if (idx >= NGATH/4) return;
        int e4 = idx*4;
        int i0 = e4 % IN_PAD;
        int r  = (e4 / IN_PAD) % ROWSP;
        int b  = e4 / (IN_PAD*ROWSP);
        float v0 = 0.f, v1 = 0.f, v2 = 0.f, v3 = 0.f;
        if (r >= 1 && r <= T_ && i0 < IN_DIM_) {
            int m = b*T_ + (r-1);
            float mv = mask[m];
            if (mv != 0.f) {
                if (i0 + 3 < WD_) {
                    float4 x = *reinterpret_cast<const float4*>(&wemb[words[m]*WD_ + i0]);
                    v0 = x.x; v1 = x.y; v2 = x.z; v3 = x.w;
                } else {
                    int wd = words[m], i1 = d1i[m], i2 = d2i[m];
                    float t[4];
                    #pragma unroll
                    for (int j = 0; j < 4; ++j) {
                        int i = i0 + j;
                        float x;
                        if (i < WD_)            x = wemb[wd*WD_ + i];
                        else if (i < WD_+DD_)   x = d1e[i1*DD_ + (i - WD_)];
                        else                    x = d2e[i2*DD_ + (i - WD_ - DD_)];
                        t[j] = x;
                    }
                    v0 = t[0]; v1 = t[1]; v2 = t[2]; v3 = t[3];
                }
                v0 *= mv; v1 *= mv; v2 *= mv; v3 *= mv;
            }
        }
        reinterpret_cast<uint2*>(g_inpb)[idx] = pack4(v0, v1, v2, v3);
    } else if (bid < NB_GATH + NB_PREP) {
        int idx = (bid - NB_GATH)*256 + threadIdx.x;
        if (idx >= NPREP/4) return;
        int e4 = idx*4;
        if (e4 < NWT) {
            int o = e4 / KC3, k0 = e4 % KC3;
            float v0 = 0.f, v1 = 0.f, v2 = 0.f, v3 = 0.f;
            if (k0 < 1248) {
                int h = k0 / 416, i0 = k0 - h*416;
                if (i0 < 400) {
                    const float* src = &conv_w[o*1200 + i0*3 + h];
                    v0 = src[0]; v1 = src[3]; v2 = src[6]; v3 = src[9];
                }
            }
            reinterpret_cast<uint2*>(g_Wth)[idx] = pack4(v0, v1, v2, v3);
        } else if (e4 < NWT + NWAC) {
            int r = e4 - NWT;
            int ep = r / KA2, i0 = r % KA2;      // combined row e' in [0,1408)
            float v0 = 0.f, v1 = 0.f, v2 = 0.f, v3 = 0.f;
            if (ep < 2*ATTN_ && i0 < IN_DIM_) {
                int w = ep >= ATTN_;
                int e = ep - w*ATTN_;
                const float* Wa = w ? Wa2 : Wa1;
                float4 x = *reinterpret_cast<const float4*>(&Wa[e*ATTN_ + i0]);
                v0 = x.x; v1 = x.y; v2 = x.z; v3 = x.w;
            }
            reinterpret_cast<uint2*>(g_WaTh)[r/4] = pack4(v0, v1, v2, v3);
        } else {
            int j4 = e4 - NWT - NWAC;
            int w = j4 / NW2;
            int r = j4 % NW2;
            int e = r / KE_, i0 = r % KE_;
            float v0 = 0.f, v1 = 0.f, v2 = 0.f, v3 = 0.f;
            if (e < ATTN_ && i0 < WD_) {
                const float* Wa = w ? Wa2 : Wa1;
                float4 x = *reinterpret_cast<const float4*>(&Wa[e*ATTN_ + IN_DIM_ + i0]);
                v0 = x.x; v1 = x.y; v2 = x.z; v3 = x.w;
            }
            reinterpret_cast<uint2*>(g_Wa2h)[j4/4] = pack4(v0, v1, v2, v3);
        }
    } else if (bid < NB_GATH + NB_PREP + NB_ARGE) {
        int idx = (bid - NB_GATH - NB_PREP)*256 + threadIdx.x;
        if (idx >= NARGE/4) return;
        int e4 = idx*4;
        int i0 = e4 % KE_;
        int b  = (e4 / KE_) % B_;
        int w  = e4 / (B_*KE_);
        const int* arg = w ? arg2 : arg1;
        float v0 = 0.f, v1 = 0.f, v2 = 0.f, v3 = 0.f;
        if (i0 < WD_) {
            float4 x = *reinterpret_cast<const float4*>(&wemb[arg[b]*WD_ + i0]);
            v0 = x.x; v1 = x.y; v2 = x.z; v3 = x.w;
        }
        reinterpret_cast<uint2*>(g_argb)[idx] = pack4(v0, v1, v2, v3);
    } else {
        // combined wr
        int idx = (bid - NB_GATH - NB_PREP - NB_ARGE)*256 + threadIdx.x;
        if (idx >= NA_CM/4) return;
        int e4 = idx*4;
        float4 v = make_float4(0.f, 0.f, 0.f, 0.f);
        if (e4 < ATTN_)            v = *reinterpret_cast<const float4*>(&wr1[e4]);
        else if (e4 < 2*ATTN_)     v = *reinterpret_cast<const float4*>(&wr2[e4 - ATTN_]);
        *reinterpret_cast<float4*>(&g_wrc[e4]) = v;
    }
}

// ---------------- unified bf16 GEMM: cgemm / conv / attn(combined) ----------------
__global__ __launch_bounds__(256, 2) void k_gemm() {
    extern __shared__ float smem[];
    uint32_t sb = (uint32_t)__cvta_generic_to_shared(smem);

    int bid = blockIdx.x;
    int tid = threadIdx.x;
    int lane = tid & 31, warp = tid >> 5;
    int warpM = warp & 1, warpN = warp >> 1;
    int g = lane >> 2, t = lane & 3;

    float acc[4][4][4];
    #pragma unroll
    for (int mi = 0; mi < 4; ++mi)
        #pragma unroll
        for (int ni = 0; ni < 4; ++ni)
            #pragma unroll
            for (int c = 0; c < 4; ++c) acc[mi][ni][c] = 0.f;

    uint32_t abuf[NSTG], bbuf[NSTG];
    #pragma unroll
    for (int s = 0; s < NSTG; ++s) {
        abuf[s] = sb + (uint32_t)(2*s)*TILE_B;
        bbuf[s] = sb + (uint32_t)(2*s + 1)*TILE_B;
    }

    int mode;                        // 2 cgemm, 0 conv, 1 attn
    int b = 0, n0, NT;
    const __nv_bfloat16* Bsrc;
    const __nv_bfloat16* Aexp = 0;
    int BK;
    int w = 0, chunk = 0, mt = 0;
    if (bid < NB_CG) {
        mode = 2;
        w = bid / 12;
        int r = bid % 12;
        mt = r / 6;
        chunk = r % 6;
        n0 = chunk * 128;
        NT = 5;
        Bsrc = &g_Wa2h[w*NW2];
        BK = KE_;
        Aexp = &g_argb[(w*B_ + mt*128)*KE_];
    } else if (bid < NB_CG + NB_CONV) {
        mode = 0;
        int id = bid - NB_CG;
        n0 = (id & 3) << 7;
        b  = id >> 2;
        NT = NSC_C/2;
        Bsrc = g_Wth;
        BK = KC3;
    } else {
        mode = 1;
        int id = bid - NB_CG - NB_CONV;
        b = id / NCH_A;
        chunk = id % NCH_A;
        n0 = chunk * 128;
        NT = 7;
        Bsrc = g_WaTh;
        BK = KA2;
    }

    int l_row = tid >> 2, l_grp = tid & 3;
    int l_row2 = (tid + 256) >> 2, l_grp2 = (tid + 256) & 3;

    auto load_stage = [&](int st, int s) {
        #pragma unroll
        for (int sub = 0; sub < 2; ++sub) {
            int sc = 2*st + sub;
            const __nv_bfloat16* aptr;
            int astride;
            if (mode == 0) {
                int h, i0;
                if (sc < 39) { h = sc / 13; i0 = (sc - h*13) * 32; }
                else         { h = 0; i0 = 0; }
                aptr = &g_inpb[(b*ROWSP + h)*IN_PAD + i0];
                astride = IN_PAD;
            } else if (mode == 1) {
                int i0 = (sc < 13) ? sc*32 : 0;
                aptr = &g_inpb[(b*ROWSP + 1)*IN_PAD + i0];
                astride = IN_PAD;
            } else {
                aptr = Aexp + sc*32;
                astride = KE_;
            }
            int k0 = sc * 32;
            uint32_t colb = (uint32_t)(sub * 64);
            cpa16(abuf[s] + (uint32_t)(l_row*LDAB) + colb + (uint32_t)(l_grp*16),
                  aptr + l_row*astride + l_grp*8);
            cpa16(bbuf[s] + (uint32_t)(l_row*LDAB) + colb + (uint32_t)(l_grp*16),
                  &Bsrc[(n0 + l_row)*BK + k0 + l_grp*8]);
            cpa16(abuf[s] + (uint32_t)(l_row2*LDAB) + colb + (uint32_t)(l_grp2*16),
                  aptr + l_row2*astride + l_grp2*8);
            cpa16(bbuf[s] + (uint32_t)(l_row2*LDAB) + colb + (uint32_t)(l_grp2*16),
                  &Bsrc[(n0 + l_row2)*BK + k0 + l_grp2*8]);
        }
        CP_COMMIT();
    };

    uint32_t a_off[4], b_off[2];
    #pragma unroll
    for (int mi = 0; mi < 4; ++mi) {
        int row = warpM*64 + mi*16 + (lane & 15);
        a_off[mi] = (uint32_t)(row*LDAB + ((lane >> 4) << 4));
    }
    #pragma unroll
    for (int nip = 0; nip < 2; ++nip) {
        int row = warpN*32 + nip*16 + (lane & 7) + ((lane >> 4) << 3);
        b_off[nip] = (uint32_t)(row*LDAB + (((lane >> 3) & 1) << 4));
    }

    load_stage(0, 0);
    load_stage(1, 1);

    int s = 0;
    for (int st = 0; st < NT; ++st) {
        CP_WAIT(1);
        __syncthreads();
        if (st + 2 < NT) {
            int s2 = s + 2; if (s2 >= NSTG) s2 -= NSTG;
            load_stage(st + 2, s2);
        } else {
            CP_COMMIT();
        }
        #pragma unroll
        for (int ks = 0; ks < 4; ++ks) {
            uint32_t af[4][4], bf[4][2];
            #pragma unroll
            for (int mi = 0; mi < 4; ++mi)
                ldsm4(af[mi], abuf[s] + a_off[mi] + ks*32);
            #pragma unroll
            for (int nip = 0; nip < 2; ++nip)
                ldsm4(&bf[2*nip][0], bbuf[s] + b_off[nip] + ks*32);
            #pragma unroll
            for (int mi = 0; mi < 4; ++mi)
                #pragma unroll
                for (int ni = 0; ni < 4; ++ni)
                    MMA_BF16(acc[mi][ni], af[mi], bf[ni]);
        }
        if (++s >= NSTG) s = 0;
    }
    __syncthreads();

    if (mode == 0) {
        float cm[4][2];
        #pragma unroll
        for (int ni = 0; ni < 4; ++ni) { cm[ni][0] = -1e30f; cm[ni][1] = -1e30f; }
        #pragma unroll
        for (int mi = 0; mi < 4; ++mi)
            #pragma unroll
            for (int ni = 0; ni < 4; ++ni) {
                cm[ni][0] = fmaxf(cm[ni][0], fmaxf(acc[mi][ni][0], acc[mi][ni][2]));
                cm[ni][1] = fmaxf(cm[ni][1], fmaxf(acc[mi][ni][1], acc[mi][ni][3]));
            }
        #pragma unroll
        for (int off = 4; off < 32; off <<= 1)
            #pragma unroll
            for (int ni = 0; ni < 4; ++ni) {
                cm[ni][0] = fmaxf(cm[ni][0], __shfl_xor_sync(0xffffffffu, cm[ni][0], off));
                cm[ni][1] = fmaxf(cm[ni][1], __shfl_xor_sync(0xffffffffu, cm[ni][1], off));
            }
        float* smax = smem;
        if (g == 0) {
            #pragma unroll
            for (int ni = 0; ni < 4; ++ni) {
                int col = warpN*32 + ni*8 + 2*t;
                smax[warpM*128 + col]     = cm[ni][0];
                smax[warpM*128 + col + 1] = cm[ni][1];
            }
        }
        __syncthreads();
        if (tid < 128)
            g_cnnmax[b*NF_ + n0 + tid] = fmaxf(smax[tid], smax[128 + tid]);
    } else if (mode == 1) {
        if (tid == 0) {
            while (atomicAdd(&g_cflag, 0) < NB_CG) { }
        }
        __syncthreads();
        __threadfence();
        // per-thread c/wr for this thread's 8 combined columns
        float cv[4][2], wv[4][2];
        bool hi[4][2];
        #pragma unroll
        for (int ni = 0; ni < 4; ++ni)
            #pragma unroll
            for (int c = 0; c < 2; ++c) {
                int col = n0 + warpN*32 + ni*8 + 2*t + c;   // < 1408
                cv[ni][c] = g_cc[b*NA_CM + col];
                wv[ni][c] = g_wrc[col];
                hi[ni][c] = col >= ATTN_;
            }
        float ra0[4][2], ra1[4][2];
        #pragma unroll
        for (int mi = 0; mi < 4; ++mi) {
            #pragma unroll
            for (int rr = 0; rr < 2; ++rr) {
                float r0 = 0.f, r1 = 0.f;
                #pragma unroll
                for (int ni = 0; ni < 4; ++ni)
                    #pragma unroll
                    for (int c = 0; c < 2; ++c) {
                        float term = wv[ni][c] * tanhf(acc[mi][ni][rr*2 + c] + cv[ni][c]);
                        if (hi[ni][c]) r1 += term; else r0 += term;
                    }
                ra0[mi][rr] = r0;
                ra1[mi][rr] = r1;
            }
        }
        #pragma unroll
        for (int off = 1; off < 4; off <<= 1)
            #pragma unroll
            for (int mi = 0; mi < 4; ++mi)
                #pragma unroll
                for (int rr = 0; rr < 2; ++rr) {
                    ra0[mi][rr] += __shfl_xor_sync(0xffffffffu, ra0[mi][rr], off);
                    ra1[mi][rr] += __shfl_xor_sync(0xffffffffu, ra1[mi][rr], off);
                }
        float* red0 = smem;          // [4][128]
        float* red1 = smem + 512;    // [4][128]
        if (t == 0) {
            #pragma unroll
            for (int mi = 0; mi < 4; ++mi)
                #pragma unroll
                for (int rr = 0; rr < 2; ++rr) {
                    int row = warpM*64 + mi*16 + g + rr*8;
                    red0[warpN*128 + row] = ra0[mi][rr];
                    red1[warpN*128 + row] = ra1[mi][rr];
                }
        }
        __syncthreads();
        if (tid < 128) {
            float s0 = red0[tid] + red0[128 + tid] + red0[256 + tid] + red0[384 + tid];
            float s1 = red1[tid] + red1[128 + tid] + red1[256 + tid] + red1[384 + tid];
            g_spart[(chunk*2 + 0)*M_ + b*T_ + tid] = s0;
            g_spart[(chunk*2 + 1)*M_ + b*T_ + tid] = s1;
        }
    } else {
        // cgemm: store into combined c layout, then signal
        #pragma unroll
        for (int mi = 0; mi < 4; ++mi)
            #pragma unroll
            for (int rr = 0; rr < 2; ++rr) {
                int bb = mt*128 + warpM*64 + mi*16 + g + rr*8;
                #pragma unroll
                for (int ni = 0; ni < 4; ++ni)
                    #pragma unroll
                    for (int c = 0; c < 2; ++c) {
                        int col = n0 + warpN*32 + ni*8 + 2*t + c;
                        if (col < ATTN_)
                            g_cc[bb*NA_CM + w*ATTN_ + col] = acc[mi][ni][rr*2 + c];
                    }
            }
        __threadfence();
        __syncthreads();
        if (tid == 0) atomicAdd(&g_cflag, 1);
    }
}

// ---------------- fused softmax + wsum + final dense + softmax ----------------
__global__ __launch_bounds__(512) void k_post(const float* __restrict__ mask,
                                              const float* __restrict__ conv_b,
                                              const float* __restrict__ dw,
                                              const float* __restrict__ db,
                                              float* __restrict__ out) {
    int b = blockIdx.x;
    int tid = threadIdx.x;
    __shared__ float aw[2][128];
    __shared__ float sh[2][128];
    __shared__ float feat[FEAT_];
    __shared__ float lg[NCLS_];
    int w = (tid >> 7) & 1, t = tid & 127;

    float s = 0.f, e = 0.f;
    if (tid < 256) {
        #pragma unroll
        for (int c = 0; c < NCH_A; ++c) s += g_spart[(c*2 + w)*M_ + b*T_ + t];
        if (mask[b*T_ + t] == 0.f) s = -1e30f;
        sh[w][t] = s;
    }
    __syncthreads();
    for (int o = 64; o > 0; o >>= 1) {
        if (tid < 256 && t < o) sh[w][t] = fmaxf(sh[w][t], sh[w][t + o]);
        __syncthreads();
    }
    float mx = (tid < 256) ? sh[w][0] : 0.f;
    __syncthreads();
    if (tid < 256) { e = expf(s - mx); sh[w][t] = e; }
    __syncthreads();
    for (int o = 64; o > 0; o >>= 1) {
        if (tid < 256 && t < o) sh[w][t] += sh[w][t + o];
        __syncthreads();
    }
    if (tid < 256) aw[w][t] = e / sh[w][0];
    __syncthreads();

    for (int idx = tid; idx < 2*IN_DIM_; idx += 512) {
        int w2 = idx / IN_DIM_, d = idx % IN_DIM_;
        float s2 = 0.f;
        #pragma unroll 4
        for (int t2 = 0; t2 < T_; ++t2)
            s2 += aw[w2][t2] * __bfloat162float(g_inpb[(b*ROWSP + t2 + 1)*IN_PAD + d]);
        feat[NF_ + idx] = s2;
    }
    feat[tid] = tanhf(g_cnnmax[b*NF_ + tid] + conv_b[tid]);
    __syncthreads();

    int warp = tid >> 5, lane = tid & 31;
    for (int c = warp; c < NCLS_; c += 16) {
        float s3 = 0.f;
        for (int i = lane; i < FEAT_; i += 32) s3 += feat[i] * dw[c*FEAT_ + i];
        #pragma unroll
        for (int off = 16; off > 0; off >>= 1)
            s3 += __shfl_xor_sync(0xffffffffu, s3, off);
        if (lane == 0) lg[c] = s3 + db[c];
    }
    __syncthreads();
    if (tid == 0) {
        float mx2 = lg[0];
        #pragma unroll
        for (int c = 1; c < NCLS_; ++c) mx2 = fmaxf(mx2, lg[c]);
        float sm = 0.f, ee[NCLS_];
        #pragma unroll
        for (int c = 0; c < NCLS_; ++c) { ee[c] = expf(lg[c] - mx2); sm += ee[c]; }
        #pragma unroll
        for (int c = 0; c < NCLS_; ++c) out[b*NCLS_ + c] = ee[c] / sm;
    }
}

// ---------------- launch ----------------
extern "C" void kernel_launch(void* const* d_in, const int* in_sizes, int n_in,
                              void* d_out, int out_size) {
    const int*   words  = (const int*)d_in[0];
    const float* mask   = (const float*)d_in[1];
    const int*   d1i    = (const int*)d_in[2];
    const int*   d2i    = (const int*)d_in[3];
    const int*   arg1   = (const int*)d_in[7];
    const int*   arg2   = (const int*)d_in[8];
    const float* wemb   = (const float*)d_in[9];
    const float* d1e    = (const float*)d_in[10];
    const float* d2e    = (const float*)d_in[11];
    const float* Wa1    = (const float*)d_in[12];
    const float* wr1    = (const float*)d_in[13];
    const float* Wa2    = (const float*)d_in[14];
    const float* wr2    = (const float*)d_in[15];
    const float* conv_w = (const float*)d_in[16];
    const float* conv_b = (const float*)d_in[17];
    const float* dw     = (const float*)d_in[18];
    const float* db     = (const float*)d_in[19];
    float* out = (float*)d_out;

    cudaFuncSetAttribute(k_gemm, cudaFuncAttributeMaxDynamicSharedMemorySize, SMEM_BYTES);

    k_init<<<NB_INIT, 256>>>(words, d1i, d2i, wemb, d1e, d2e, mask,
                             conv_w, Wa1, Wa2, arg1, arg2, wr1, wr2);
    k_gemm<<<NB_GEMM, 256, SMEM_BYTES>>>();
    k_post<<<B_, 512>>>(mask, conv_b, dw, db, out);
}

// round 16
// speedup vs baseline: 1.1425x; 1.0134x over previous
#include <cuda_runtime.h>
#include <cuda_bf16.h>
#include <math.h>
#include <stdint.h>

#define B_    256
#define T_    128
#define WD_   300
#define DD_   50
#define IN_DIM_ 400
#define IN_PAD  416
#define ROWSP   130
#define ATTN_ 700
#define NA_CM 1408                 // combined attn N (2*700 padded to 11*128)
#define NCH_A 11
#define NPC   768                  // cgemm N padding
#define KC3   1280
#define KA2   448
#define KE_   320
#define NSC_C 40
#define NF_   512
#define NCLS_ 19
#define M_    (B_*T_)
#define FEAT_ (NF_ + 2*IN_DIM_)
#define LDAB  144
#define TILE_B (128*LDAB)
#define NSTG  3
#define SMEM_BYTES (NSTG*2*TILE_B) // 110592

// grid: [0,24) cgemm, [24,1048) conv, [1048, 1048+2816) attn
#define NB_CG   24
#define NB_CONV 1024
#define NB_ATTN (B_*NCH_A)
#define NB_GEMM (NB_CG + NB_CONV + NB_ATTN)

// k_init segments (unit = 8 elements)
#define NWT   (NF_*KC3)
#define NWAC  (NA_CM*KA2)
#define NW2   (NPC*KE_)
#define NPREP (NWT + NWAC + 2*NW2)
#define NGATH (B_*ROWSP*IN_PAD)
#define NARGE (2*B_*KE_)
#define NB_GATH ((NGATH/8 + 255)/256)
#define NB_PREP ((NPREP/8 + 255)/256)
#define NB_ARGE ((NARGE/8 + 255)/256)
#define NB_WRC  ((NA_CM/8 + 255)/256)
#define NB_INIT (NB_GATH + NB_PREP + NB_ARGE + NB_WRC)

// ---------------- scratch ----------------
__device__ __nv_bfloat16  g_inpb[B_*ROWSP*IN_PAD];
__device__ __nv_bfloat16  g_Wth[NF_*KC3];
__device__ __nv_bfloat16  g_WaTh[NA_CM*KA2];         // combined [e'][i]
__device__ __nv_bfloat16  g_Wa2h[2*NPC*KE_];
__device__ __nv_bfloat16  g_argb[2*B_*KE_];
__device__ float g_cc[B_*NA_CM];                     // combined c [b][w*700+e]
__device__ float g_wrc[NA_CM];                       // combined wr
__device__ float g_spart[2*NCH_A*M_];                // plane = chunk*2 + w
__device__ float g_cnnmax[B_*NF_];
__device__ int   g_cflag;

__device__ __forceinline__ void cpa16(uint32_t dst, const void* src) {
    asm volatile("cp.async.cg.shared.global [%0], [%1], 16;\n" :: "r"(dst), "l"(src));
}
#define CP_COMMIT() asm volatile("cp.async.commit_group;\n")
#define CP_WAIT(n)  asm volatile("cp.async.wait_group %0;\n" :: "n"(n))

__device__ __forceinline__ void ldsm4(uint32_t* r, uint32_t a) {
    asm volatile("ldmatrix.sync.aligned.m8n8.x4.shared.b16 {%0,%1,%2,%3}, [%4];"
        : "=r"(r[0]), "=r"(r[1]), "=r"(r[2]), "=r"(r[3]) : "r"(a));
}

#define MMA_BF16(c, a, b) \
    asm volatile("mma.sync.aligned.m16n8k16.row.col.f32.bf16.bf16.f32 " \
        "{%0,%1,%2,%3},{%4,%5,%6,%7},{%8,%9},{%0,%1,%2,%3};" \
        : "+f"(c[0]), "+f"(c[1]), "+f"(c[2]), "+f"(c[3]) \
        : "r"(a[0]), "r"(a[1]), "r"(a[2]), "r"(a[3]), "r"(b[0]), "r"(b[1]))

__device__ __forceinline__ uint4 pack8(const float* v) {
    __nv_bfloat162 p0 = __floats2bfloat162_rn(v[0], v[1]);
    __nv_bfloat162 p1 = __floats2bfloat162_rn(v[2], v[3]);
    __nv_bfloat162 p2 = __floats2bfloat162_rn(v[4], v[5]);
    __nv_bfloat162 p3 = __floats2bfloat162_rn(v[6], v[7]);
    uint4 r;
    r.x = *reinterpret_cast<uint32_t*>(&p0);
    r.y = *reinterpret_cast<uint32_t*>(&p1);
    r.z = *reinterpret_cast<uint32_t*>(&p2);
    r.w = *reinterpret_cast<uint32_t*>(&p3);
    return r;
}

// ---------------- k_init: 8 elements/thread, vectorized ----------------
__global__ void k_init(const int* __restrict__ words,
                       const int* __restrict__ d1i,
                       const int* __restrict__ d2i,
                       const float* __restrict__ wemb,
                       const float* __restrict__ d1e,
                       const float* __restrict__ d2e,
                       const float* __restrict__ mask,
                       const float* __restrict__ conv_w,
                       const float* __restrict__ Wa1,
                       const float* __restrict__ Wa2,
                       const int* __restrict__ arg1,
                       const int* __restrict__ arg2,
                       const float* __restrict__ wr1,
                       const float* __restrict__ wr2) {
    int bid = blockIdx.x;
    if (bid == 0 && threadIdx.x == 0) g_cflag = 0;
    float v[8];
    #pragma unroll
    for (int j = 0; j < 8; ++j) v[j] = 0.f;

    if (bid < NB_GATH) {
        int idx = bid*256 + threadIdx.x;
        if (idx >= NGATH/8) return;
        int e8 = idx*8;
        int i0 = e8 % IN_PAD;                 // multiple of 8
        int r  = (e8 / IN_PAD) % ROWSP;
        int b  = e8 / (IN_PAD*ROWSP);
        if (r >= 1 && r <= T_ && i0 < IN_DIM_) {
            int m = b*T_ + (r-1);
            float mv = mask[m];
            if (mv != 0.f) {
                if (i0 + 7 < WD_) {           // fast path: word region
                    float4 x0 = *reinterpret_cast<const float4*>(&wemb[words[m]*WD_ + i0]);
                    float4 x1 = *reinterpret_cast<const float4*>(&wemb[words[m]*WD_ + i0 + 4]);
                    v[0]=x0.x; v[1]=x0.y; v[2]=x0.z; v[3]=x0.w;
                    v[4]=x1.x; v[5]=x1.y; v[6]=x1.z; v[7]=x1.w;
                } else {
                    int wd = words[m], i1 = d1i[m], i2 = d2i[m];
                    #pragma unroll
                    for (int j = 0; j < 8; ++j) {
                        int i = i0 + j;
                        if (i < WD_)            v[j] = wemb[wd*WD_ + i];
                        else if (i < WD_+DD_)   v[j] = d1e[i1*DD_ + (i - WD_)];
                        else                    v[j] = d2e[i2*DD_ + (i - WD_ - DD_)];
                    }
                }
                #pragma unroll
                for (int j = 0; j < 8; ++j) v[j] *= mv;
            }
        }
        reinterpret_cast<uint4*>(g_inpb)[idx] = pack8(v);
    } else if (bid < NB_GATH + NB_PREP) {
        int idx = (bid - NB_GATH)*256 + threadIdx.x;
        if (idx >= NPREP/8) return;
        int e8 = idx*8;
        if (e8 < NWT) {
            int o = e8 / KC3, k0 = e8 % KC3;   // chunk-uniform (416|8, 400|8, 1248|8)
            if (k0 < 1248) {
                int h = k0 / 416, i0 = k0 - h*416;
                if (i0 < 400) {
                    const float* src = &conv_w[o*1200 + i0*3 + h];
                    #pragma unroll
                    for (int j = 0; j < 8; ++j) v[j] = src[3*j];
                }
            }
            reinterpret_cast<uint4*>(g_Wth)[idx] = pack8(v);
        } else if (e8 < NWT + NWAC) {
            int r = e8 - NWT;
            int ep = r / KA2, i0 = r % KA2;      // uniform (448|8, 400|8)
            if (ep < 2*ATTN_ && i0 < IN_DIM_) {
                int w = ep >= ATTN_;
                int e = ep - w*ATTN_;
                const float* Wa = w ? Wa2 : Wa1;
                float4 x0 = *reinterpret_cast<const float4*>(&Wa[e*ATTN_ + i0]);
                float4 x1 = *reinterpret_cast<const float4*>(&Wa[e*ATTN_ + i0 + 4]);
                v[0]=x0.x; v[1]=x0.y; v[2]=x0.z; v[3]=x0.w;
                v[4]=x1.x; v[5]=x1.y; v[6]=x1.z; v[7]=x1.w;
            }
            reinterpret_cast<uint4*>(g_WaTh)[r/8] = pack8(v);
        } else {
            int j4 = e8 - NWT - NWAC;
            int w = j4 / NW2;
            int r = j4 % NW2;
            int e = r / KE_, i0 = r % KE_;       // uniform segments (320|8)
            if (e < ATTN_) {
                const float* Wa = w ? Wa2 : Wa1;
                if (i0 + 7 < WD_) {
                    float4 x0 = *reinterpret_cast<const float4*>(&Wa[e*ATTN_ + IN_DIM_ + i0]);
                    float4 x1 = *reinterpret_cast<const float4*>(&Wa[e*ATTN_ + IN_DIM_ + i0 + 4]);
                    v[0]=x0.x; v[1]=x0.y; v[2]=x0.z; v[3]=x0.w;
                    v[4]=x1.x; v[5]=x1.y; v[6]=x1.z; v[7]=x1.w;
                } else if (i0 < WD_) {
                    #pragma unroll
                    for (int j = 0; j < 8; ++j)
                        if (i0 + j < WD_) v[j] = Wa[e*ATTN_ + IN_DIM_ + i0 + j];
                }
            }
            reinterpret_cast<uint4*>(g_Wa2h)[j4/8] = pack8(v);
        }
    } else if (bid < NB_GATH + NB_PREP + NB_ARGE) {
        int idx = (bid - NB_GATH - NB_PREP)*256 + threadIdx.x;
        if (idx >= NARGE/8) return;
        int e8 = idx*8;
        int i0 = e8 % KE_;
        int b  = (e8 / KE_) % B_;
        int w  = e8 / (B_*KE_);
        const int* arg = w ? arg2 : arg1;
        if (i0 + 7 < WD_) {
            float4 x0 = *reinterpret_cast<const float4*>(&wemb[arg[b]*WD_ + i0]);
            float4 x1 = *reinterpret_cast<const float4*>(&wemb[arg[b]*WD_ + i0 + 4]);
            v[0]=x0.x; v[1]=x0.y; v[2]=x0.z; v[3]=x0.w;
            v[4]=x1.x; v[5]=x1.y; v[6]=x1.z; v[7]=x1.w;
        } else if (i0 < WD_) {
            int a = arg[b];
            #pragma unroll
            for (int j = 0; j < 8; ++j)
                if (i0 + j < WD_) v[j] = wemb[a*WD_ + i0 + j];
        }
        reinterpret_cast<uint4*>(g_argb)[idx] = pack8(v);
    } else {
        // combined wr (tiny; elementwise, 700-boundary straddles 8-blocks)
        int idx = (bid - NB_GATH - NB_PREP - NB_ARGE)*256 + threadIdx.x;
        if (idx >= NA_CM/8) return;
        int e8 = idx*8;
        #pragma unroll
        for (int j = 0; j < 8; ++j) {
            int e = e8 + j;
            float x = 0.f;
            if (e < ATTN_)          x = wr1[e];
            else if (e < 2*ATTN_)   x = wr2[e - ATTN_];
            g_wrc[e] = x;
        }
    }
}

// ---------------- unified bf16 GEMM: cgemm / conv / attn(combined) ----------------
__global__ __launch_bounds__(256, 2) void k_gemm() {
    extern __shared__ float smem[];
    uint32_t sb = (uint32_t)__cvta_generic_to_shared(smem);

    int bid = blockIdx.x;
    int tid = threadIdx.x;
    int lane = tid & 31, warp = tid >> 5;
    int warpM = warp & 1, warpN = warp >> 1;
    int g = lane >> 2, t = lane & 3;

    float acc[4][4][4];
    #pragma unroll
    for (int mi = 0; mi < 4; ++mi)
        #pragma unroll
        for (int ni = 0; ni < 4; ++ni)
            #pragma unroll
            for (int c = 0; c < 4; ++c) acc[mi][ni][c] = 0.f;

    uint32_t abuf[NSTG], bbuf[NSTG];
    #pragma unroll
    for (int s = 0; s < NSTG; ++s) {
        abuf[s] = sb + (uint32_t)(2*s)*TILE_B;
        bbuf[s] = sb + (uint32_t)(2*s + 1)*TILE_B;
    }

    int mode;                        // 2 cgemm, 0 conv, 1 attn
    int b = 0, n0, NT;
    const __nv_bfloat16* Bsrc;
    const __nv_bfloat16* Aexp = 0;
    int BK;
    int w = 0, chunk = 0, mt = 0;
    if (bid < NB_CG) {
        mode = 2;
        w = bid / 12;
        int r = bid % 12;
        mt = r / 6;
        chunk = r % 6;
        n0 = chunk * 128;
        NT = 5;
        Bsrc = &g_Wa2h[w*NW2];
        BK = KE_;
        Aexp = &g_argb[(w*B_ + mt*128)*KE_];
    } else if (bid < NB_CG + NB_CONV) {
        mode = 0;
        int id = bid - NB_CG;
        n0 = (id & 3) << 7;
        b  = id >> 2;
        NT = NSC_C/2;
        Bsrc = g_Wth;
        BK = KC3;
    } else {
        mode = 1;
        int id = bid - NB_CG - NB_CONV;
        b = id / NCH_A;
        chunk = id % NCH_A;
        n0 = chunk * 128;
        NT = 7;
        Bsrc = g_WaTh;
        BK = KA2;
    }

    int l_row = tid >> 2, l_grp = tid & 3;
    int l_row2 = (tid + 256) >> 2, l_grp2 = (tid + 256) & 3;

    auto load_stage = [&](int st, int s) {
        #pragma unroll
        for (int sub = 0; sub < 2; ++sub) {
            int sc = 2*st + sub;
            const __nv_bfloat16* aptr;
            int astride;
            if (mode == 0) {
                int h, i0;
                if (sc < 39) { h = sc / 13; i0 = (sc - h*13) * 32; }
                else         { h = 0; i0 = 0; }
                aptr = &g_inpb[(b*ROWSP + h)*IN_PAD + i0];
                astride = IN_PAD;
            } else if (mode == 1) {
                int i0 = (sc < 13) ? sc*32 : 0;
                aptr = &g_inpb[(b*ROWSP + 1)*IN_PAD + i0];
                astride = IN_PAD;
            } else {
                aptr = Aexp + sc*32;
                astride = KE_;
            }
            int k0 = sc * 32;
            uint32_t colb = (uint32_t)(sub * 64);
            cpa16(abuf[s] + (uint32_t)(l_row*LDAB) + colb + (uint32_t)(l_grp*16),
                  aptr + l_row*astride + l_grp*8);
            cpa16(bbuf[s] + (uint32_t)(l_row*LDAB) + colb + (uint32_t)(l_grp*16),
                  &Bsrc[(n0 + l_row)*BK + k0 + l_grp*8]);
            cpa16(abuf[s] + (uint32_t)(l_row2*LDAB) + colb + (uint32_t)(l_grp2*16),
                  aptr + l_row2*astride + l_grp2*8);
            cpa16(bbuf[s] + (uint32_t)(l_row2*LDAB) + colb + (uint32_t)(l_grp2*16),
                  &Bsrc[(n0 + l_row2)*BK + k0 + l_grp2*8]);
        }
        CP_COMMIT();
    };

    uint32_t a_off[4], b_off[2];
    #pragma unroll
    for (int mi = 0; mi < 4; ++mi) {
        int row = warpM*64 + mi*16 + (lane & 15);
        a_off[mi] = (uint32_t)(row*LDAB + ((lane >> 4) << 4));
    }
    #pragma unroll
    for (int nip = 0; nip < 2; ++nip) {
        int row = warpN*32 + nip*16 + (lane & 7) + ((lane >> 4) << 3);
        b_off[nip] = (uint32_t)(row*LDAB + (((lane >> 3) & 1) << 4));
    }

    load_stage(0, 0);
    load_stage(1, 1);

    int s = 0;
    for (int st = 0; st < NT; ++st) {
        CP_WAIT(1);
        __syncthreads();
        if (st + 2 < NT) {
            int s2 = s + 2; if (s2 >= NSTG) s2 -= NSTG;
            load_stage(st + 2, s2);
        } else {
            CP_COMMIT();
        }
        #pragma unroll
        for (int ks = 0; ks < 4; ++ks) {
            uint32_t af[4][4], bf[4][2];
            #pragma unroll
            for (int mi = 0; mi < 4; ++mi)
                ldsm4(af[mi], abuf[s] + a_off[mi] + ks*32);
            #pragma unroll
            for (int nip = 0; nip < 2; ++nip)
                ldsm4(&bf[2*nip][0], bbuf[s] + b_off[nip] + ks*32);
            #pragma unroll
            for (int mi = 0; mi < 4; ++mi)
                #pragma unroll
                for (int ni = 0; ni < 4; ++ni)
                    MMA_BF16(acc[mi][ni], af[mi], bf[ni]);
        }
        if (++s >= NSTG) s = 0;
    }
    __syncthreads();

    if (mode == 0) {
        float cm[4][2];
        #pragma unroll
        for (int ni = 0; ni < 4; ++ni) { cm[ni][0] = -1e30f; cm[ni][1] = -1e30f; }
        #pragma unroll
        for (int mi = 0; mi < 4; ++mi)
            #pragma unroll
            for (int ni = 0; ni < 4; ++ni) {
                cm[ni][0] = fmaxf(cm[ni][0], fmaxf(acc[mi][ni][0], acc[mi][ni][2]));
                cm[ni][1] = fmaxf(cm[ni][1], fmaxf(acc[mi][ni][1], acc[mi][ni][3]));
            }
        #pragma unroll
        for (int off = 4; off < 32; off <<= 1)
            #pragma unroll
            for (int ni = 0; ni < 4; ++ni) {
                cm[ni][0] = fmaxf(cm[ni][0], __shfl_xor_sync(0xffffffffu, cm[ni][0], off));
                cm[ni][1] = fmaxf(cm[ni][1], __shfl_xor_sync(0xffffffffu, cm[ni][1], off));
            }
        float* smax = smem;
        if (g == 0) {
            #pragma unroll
            for (int ni = 0; ni < 4; ++ni) {
                int col = warpN*32 + ni*8 + 2*t;
                smax[warpM*128 + col]     = cm[ni][0];
                smax[warpM*128 + col + 1] = cm[ni][1];
            }
        }
        __syncthreads();
        if (tid < 128)
            g_cnnmax[b*NF_ + n0 + tid] = fmaxf(smax[tid], smax[128 + tid]);
    } else if (mode == 1) {
        if (tid == 0) {
            while (atomicAdd(&g_cflag, 0) < NB_CG) { }
        }
        __syncthreads();
        __threadfence();
        float cv[4][2], wv[4][2];
        bool hi[4][2];
        #pragma unroll
        for (int ni = 0; ni < 4; ++ni)
            #pragma unroll
            for (int c = 0; c < 2; ++c) {
                int col = n0 + warpN*32 + ni*8 + 2*t + c;
                cv[ni][c] = g_cc[b*NA_CM + col];
                wv[ni][c] = g_wrc[col];
                hi[ni][c] = col >= ATTN_;
            }
        float ra0[4][2], ra1[4][2];
        #pragma unroll
        for (int mi = 0; mi < 4; ++mi) {
            #pragma unroll
            for (int rr = 0; rr < 2; ++rr) {
                float r0 = 0.f, r1 = 0.f;
                #pragma unroll
                for (int ni = 0; ni < 4; ++ni)
                    #pragma unroll
                    for (int c = 0; c < 2; ++c) {
                        float term = wv[ni][c] * tanhf(acc[mi][ni][rr*2 + c] + cv[ni][c]);
                        if (hi[ni][c]) r1 += term; else r0 += term;
                    }
                ra0[mi][rr] = r0;
                ra1[mi][rr] = r1;
            }
        }
        #pragma unroll
        for (int off = 1; off < 4; off <<= 1)
            #pragma unroll
            for (int mi = 0; mi < 4; ++mi)
                #pragma unroll
                for (int rr = 0; rr < 2; ++rr) {
                    ra0[mi][rr] += __shfl_xor_sync(0xffffffffu, ra0[mi][rr], off);
                    ra1[mi][rr] += __shfl_xor_sync(0xffffffffu, ra1[mi][rr], off);
                }
        float* red0 = smem;
        float* red1 = smem + 512;
        if (t == 0) {
            #pragma unroll
            for (int mi = 0; mi < 4; ++mi)
                #pragma unroll
                for (int rr = 0; rr < 2; ++rr) {
                    int row = warpM*64 + mi*16 + g + rr*8;
                    red0[warpN*128 + row] = ra0[mi][rr];
                    red1[warpN*128 + row] = ra1[mi][rr];
                }
        }
        __syncthreads();
        if (tid < 128) {
            float s0 = red0[tid] + red0[128 + tid] + red0[256 + tid] + red0[384 + tid];
            float s1 = red1[tid] + red1[128 + tid] + red1[256 + tid] + red1[384 + tid];
            g_spart[(chunk*2 + 0)*M_ + b*T_ + tid] = s0;
            g_spart[(chunk*2 + 1)*M_ + b*T_ + tid] = s1;
        }
    } else {
        #pragma unroll
        for (int mi = 0; mi < 4; ++mi)
            #pragma unroll
            for (int rr = 0; rr < 2; ++rr) {
                int bb = mt*128 + warpM*64 + mi*16 + g + rr*8;
                #pragma unroll
                for (int ni = 0; ni < 4; ++ni)
                    #pragma unroll
                    for (int c = 0; c < 2; ++c) {
                        int col = n0 + warpN*32 + ni*8 + 2*t + c;
                        if (col < ATTN_)
                            g_cc[bb*NA_CM + w*ATTN_ + col] = acc[mi][ni][rr*2 + c];
                    }
            }
        __threadfence();
        __syncthreads();
        if (tid == 0) atomicAdd(&g_cflag, 1);
    }
}

// ---------------- fused softmax + wsum + final dense + softmax ----------------
__global__ __launch_bounds__(512) void k_post(const float* __restrict__ mask,
                                              const float* __restrict__ conv_b,
                                              const float* __restrict__ dw,
                                              const float* __restrict__ db,
                                              float* __restrict__ out) {
    int b = blockIdx.x;
    int tid = threadIdx.x;
    __shared__ float aw[2][128];
    __shared__ float sh[2][128];
    __shared__ float feat[FEAT_];
    __shared__ float lg[NCLS_];
    int w = (tid >> 7) & 1, t = tid & 127;

    float s = 0.f, e = 0.f;
    if (tid < 256) {
        #pragma unroll
        for (int c = 0; c < NCH_A; ++c) s += g_spart[(c*2 + w)*M_ + b*T_ + t];
        if (mask[b*T_ + t] == 0.f) s = -1e30f;
        sh[w][t] = s;
    }
    __syncthreads();
    for (int o = 64; o > 0; o >>= 1) {
        if (tid < 256 && t < o) sh[w][t] = fmaxf(sh[w][t], sh[w][t + o]);
        __syncthreads();
    }
    float mx = (tid < 256) ? sh[w][0] : 0.f;
    __syncthreads();
    if (tid < 256) { e = expf(s - mx); sh[w][t] = e; }
    __syncthreads();
    for (int o = 64; o > 0; o >>= 1) {
        if (tid < 256 && t < o) sh[w][t] += sh[w][t + o];
        __syncthreads();
    }
    if (tid < 256) aw[w][t] = e / sh[w][0];
    __syncthreads();

    for (int idx = tid; idx < 2*IN_DIM_; idx += 512) {
        int w2 = idx / IN_DIM_, d = idx % IN_DIM_;
        float s2 = 0.f;
        #pragma unroll 4
        for (int t2 = 0; t2 < T_; ++t2)
            s2 += aw[w2][t2] * __bfloat162float(g_inpb[(b*ROWSP + t2 + 1)*IN_PAD + d]);
        feat[NF_ + idx] = s2;
    }
    feat[tid] = tanhf(g_cnnmax[b*NF_ + tid] + conv_b[tid]);
    __syncthreads();

    int warp = tid >> 5, lane = tid & 31;
    for (int c = warp; c < NCLS_; c += 16) {
        float s3 = 0.f;
        for (int i = lane; i < FEAT_; i += 32) s3 += feat[i] * dw[c*FEAT_ + i];
        #pragma unroll
        for (int off = 16; off > 0; off >>= 1)
            s3 += __shfl_xor_sync(0xffffffffu, s3, off);
        if (lane == 0) lg[c] = s3 + db[c];
    }
    __syncthreads();
    if (tid == 0) {
        float mx2 = lg[0];
        #pragma unroll
        for (int c = 1; c < NCLS_; ++c) mx2 = fmaxf(mx2, lg[c]);
        float sm = 0.f, ee[NCLS_];
        #pragma unroll
        for (int c = 0; c < NCLS_; ++c) { ee[c] = expf(lg[c] - mx2); sm += ee[c]; }
        #pragma unroll
        for (int c = 0; c < NCLS_; ++c) out[b*NCLS_ + c] = ee[c] / sm;
    }
}

// ---------------- launch ----------------
extern "C" void kernel_launch(void* const* d_in, const int* in_sizes, int n_in,
                              void* d_out, int out_size) {
    const int*   words  = (const int*)d_in[0];
    const float* mask   = (const float*)d_in[1];
    const int*   d1i    = (const int*)d_in[2];
    const int*   d2i    = (const int*)d_in[3];
    const int*   arg1   = (const int*)d_in[7];
    const int*   arg2   = (const int*)d_in[8];
    const float* wemb   = (const float*)d_in[9];
    const float* d1e    = (const float*)d_in[10];
    const float* d2e    = (const float*)d_in[11];
    const float* Wa1    = (const float*)d_in[12];
    const float* wr1    = (const float*)d_in[13];
    const float* Wa2    = (const float*)d_in[14];
    const float* wr2    = (const float*)d_in[15];
    const float* conv_w = (const float*)d_in[16];
    const float* conv_b = (const float*)d_in[17];
    const float* dw     = (const float*)d_in[18];
    const float* db     = (const float*)d_in[19];
    float* out = (float*)d_out;

    cudaFuncSetAttribute(k_gemm, cudaFuncAttributeMaxDynamicSharedMemorySize, SMEM_BYTES);

    k_init<<<NB_INIT, 256>>>(words, d1i, d2i, wemb, d1e, d2e, mask,
                             conv_w, Wa1, Wa2, arg1, arg2, wr1, wr2);
    k_gemm<<<NB_GEMM, 256, SMEM_BYTES>>>();
    k_post<<<B_, 512>>>(mask, conv_b, dw, db, out);
}